// round 13
// baseline (speedup 1.0000x reference)
#include <cuda_runtime.h>

#define BB 8
#define NN 512
#define PP 32
#define LL 3

typedef unsigned long long ull;

// Scratch (device globals: no allocation in kernel_launch)
__device__ float g_t31[LL][BB*NN*PP];      // [l][b][n][p]
__device__ float g_nu[BB*NN*PP];           // TRANSPOSED: [b][n][p] = (t2[l]@mu_{l-1})[p][n]

// ---- packed f32x2 helpers (sm_100+) ---------------------------------------
__device__ __forceinline__ ull pk(float lo, float hi) {
    ull r; asm("mov.b64 %0,{%1,%2};" : "=l"(r) : "f"(lo), "f"(hi)); return r;
}
__device__ __forceinline__ void upk(ull v, float& lo, float& hi) {
    asm("mov.b64 {%0,%1},%2;" : "=f"(lo), "=f"(hi) : "l"(v));
}
__device__ __forceinline__ ull fma2(ull a, ull b, ull c) {
    ull d; asm("fma.rn.f32x2 %0,%1,%2,%3;" : "=l"(d) : "l"(a), "l"(b), "l"(c));
    return d;
}
__device__ __forceinline__ ull add2(ull a, ull b) {
    ull d; asm("add.rn.f32x2 %0,%1,%2;" : "=l"(d) : "l"(a), "l"(b));
    return d;
}

union F4U2 { float4 f4; ull u2[2]; };

// ---- cp.async helpers ------------------------------------------------------
__device__ __forceinline__ void cp16(float* smem_dst, const float* gsrc) {
    unsigned d = (unsigned)__cvta_generic_to_shared(smem_dst);
    asm volatile("cp.async.ca.shared.global [%0], [%1], 16;"
                 :: "r"(d), "l"(gsrc));
}
__device__ __forceinline__ void cp_commit() {
    asm volatile("cp.async.commit_group;");
}
template <int N>
__device__ __forceinline__ void cp_wait() {
    asm volatile("cp.async.wait_group %0;" :: "n"(N));
}

// ---------------------------------------------------------------------------
// K1 (fused over layers): t31[l][b][n][p] = sum_m relu(A + B*w + C*s)
//   = 0.5*(Sum v + Sum|v|);  Sum v closed-form via row sums.
// grid (N, B), block 256. lane = p; 8 warps split m; 3 layers interleaved.
// ---------------------------------------------------------------------------
__global__ __launch_bounds__(256) void edge_kernel(
    const float* __restrict__ x, const float* __restrict__ wgt,
    const float* __restrict__ t4)
{
    __shared__ float w_s[NN];
    __shared__ float s_s[NN];
    __shared__ float red_s[LL][8][PP];
    __shared__ float rw_s[8], rs_s[8];

    int n = blockIdx.x, b = blockIdx.y;
    int tid = threadIdx.x;
    int lane = tid & 31;
    int wid  = tid >> 5;

    const float* wrow = wgt + ((size_t)(b * NN + n)) * NN;
    const float* xb   = x + b * NN;

    float pw = 0.f, ps = 0.f;
    for (int m = tid; m < NN; m += 256) {
        float w = wrow[m];
        float s = 2.0f * xb[m] - 1.0f;
        w_s[m] = w;
        s_s[m] = s;
        pw += w;
        ps += s;
    }
    #pragma unroll
    for (int o = 16; o; o >>= 1) {
        pw += __shfl_xor_sync(0xffffffffu, pw, o);
        ps += __shfl_xor_sync(0xffffffffu, ps, o);
    }
    if (lane == 0) { rw_s[wid] = pw; rs_s[wid] = ps; }

    float xn = xb[n];
    float sn = 2.0f * xn - 1.0f;

    float As[LL], Bs[LL], Cs[LL];
    ull A2[LL], B2[LL], C2[LL];
    #pragma unroll
    for (int l = 0; l < LL; l++) {
        const float* t4p = t4 + (l * PP + lane) * 4;
        float c0 = t4p[0], c1 = t4p[1], c2 = t4p[2], c3 = t4p[3];
        float A  = fmaf(c0, xn, fmaf(0.5f, c2, c3));
        float C  = -0.5f * c2 * sn;
        As[l] = A; Bs[l] = c1; Cs[l] = C;
        A2[l] = pk(A, A);
        B2[l] = pk(c1, c1);
        C2[l] = pk(C, C);
    }

    __syncthreads();

    float sw = 0.f, ss = 0.f;
    #pragma unroll
    for (int k = 0; k < 8; k++) { sw += rw_s[k]; ss += rs_s[k]; }

    const ull ABSM = 0x7fffffff7fffffffULL;
    ull sa[LL] = {0, 0, 0};   // packed sum of |v|

    int m0 = wid * (NN / 8);
    #pragma unroll 4
    for (int m = m0; m < m0 + NN / 8; m += 4) {
        F4U2 w4, s4;
        w4.f4 = *(const float4*)(w_s + m);
        s4.f4 = *(const float4*)(s_s + m);
        #pragma unroll
        for (int l = 0; l < LL; l++) {
            ull v0 = fma2(C2[l], s4.u2[0], fma2(B2[l], w4.u2[0], A2[l]));
            ull v1 = fma2(C2[l], s4.u2[1], fma2(B2[l], w4.u2[1], A2[l]));
            sa[l] = add2(sa[l], add2(v0 & ABSM, v1 & ABSM));
        }
    }

    #pragma unroll
    for (int l = 0; l < LL; l++) {
        float a, bb;
        upk(sa[l], a, bb);
        red_s[l][wid][lane] = a + bb;
    }
    __syncthreads();

    if (wid < LL) {
        int l = wid;
        float stot = red_s[l][0][lane];
        #pragma unroll
        for (int k = 1; k < 8; k++) stot += red_s[l][k][lane];
        float sv = fmaf(512.0f, As[l], fmaf(Bs[l], sw, Cs[l] * ss));
        g_t31[l][(b * NN + n) * PP + lane] = 0.5f * (sv + stot);
    }
}

// ---------------------------------------------------------------------------
// K2 (per layer): full-n z + epilogue + next-layer nu, one block per (jt, b).
//   z[p][j]  = sum_n nu[b][n][p] * adj[b][n][j]       (has_z)
//   mu[p][j] = relu( term1 + z + sum_q t3[l][p][q]*t31[l][q][j] )
//   layer<2:  g_nu[b][j][p] = sum_q t2[l+1][p][q]*mu[q][j]
//   layer==2: out[b][p][j] = mu
// grid (16, 8), block 256 (8 warps). warp w -> p=4w..4w+3, lane -> j=j0+lane.
// adj read DIRECTLY from global (no reuse within block; L2-resident);
// nu staged once in smem (reused by all 8 warps). Depth-8 prefetch ring.
// ---------------------------------------------------------------------------
#define SM_NU   0                      // nu_s [512][32]
#define SM_T31  (NN*32)                // t31_s [32][33]   (scalar reads)
#define SM_T3   (SM_T31 + 32*33)       // t3t_s [32][36]   (float4 reads)
#define SM_T2N  (SM_T3 + 32*36)        // t2n_s [32][36]   (float4 reads)
#define SM_MU   (SM_T2N + 32*36)       // mu_s  [32][33]   (scalar reads)
#define SM_TOT  (SM_MU + 32*33)        // floats (~83KB)

__global__ void __launch_bounds__(256, 1) layer_kernel(
    const float* __restrict__ x, const float* __restrict__ extra,
    const float* __restrict__ adj,
    const float* __restrict__ t1, const float* __restrict__ t2,
    const float* __restrict__ t3, int layer, int has_z,
    float* __restrict__ out)
{
    extern __shared__ float sm[];
    float* nu_s  = sm + SM_NU;
    float* t31_s = sm + SM_T31;
    float* t3t_s = sm + SM_T3;
    float* t2n_s = sm + SM_T2N;
    float* mu_s  = sm + SM_MU;

    int jt = blockIdx.x, b = blockIdx.y;
    int tid  = threadIdx.x;
    int lane = tid & 31;
    int w    = tid >> 5;               // 0..7: p = 4w..4w+3
    int j0   = jt * 32;
    int j    = j0 + lane;

    if (has_z) {
        // stage nu strip [512][32]: 512 rows x 8 segs = 4096 cp16 / 256 thr
        #pragma unroll
        for (int pass = 0; pass < 16; pass++) {
            int i = tid + pass * 256;            // 0..4095
            int row = i >> 3;                    // 0..511
            int seg = (i & 7) * 4;
            cp16(&nu_s[row * 32 + seg],
                 g_nu + ((size_t)(b * NN + row)) * 32 + seg);
        }
        cp_commit();
    }

    // stage epilogue tiles (plain loads; overlap with cp.async)
    #pragma unroll
    for (int pass = 0; pass < 4; pass++) {
        int idx = tid + pass * 256;               // jl*32 + q
        int jl = idx >> 5, q = idx & 31;
        t31_s[jl * 33 + q] = g_t31[layer][((size_t)b * NN + j0 + jl) * PP + q];
    }
    #pragma unroll
    for (int pass = 0; pass < 4; pass++) {
        int idx = tid + pass * 256;               // p*32 + q
        int p = idx >> 5, q = idx & 31;
        t3t_s[q * 36 + p] = t3[layer * PP * PP + idx];
        if (layer < 2)
            t2n_s[q * 36 + p] = t2[(layer + 1) * PP * PP + idx];
    }

    if (has_z) cp_wait<0>();
    __syncthreads();

    float acc[4] = {0.f, 0.f, 0.f, 0.f};

    if (has_z) {
        const float* aptr = adj + ((size_t)b * NN) * NN + j;   // row n: + n*NN

        // depth-8 prefetch ring
        float  a_r[8];
        float4 p_r[8];
        #pragma unroll
        for (int k = 0; k < 8; k++) {
            a_r[k] = __ldg(aptr + (size_t)k * NN);
            p_r[k] = *(const float4*)&nu_s[k * 32 + w * 4];
        }

        for (int n0 = 0; n0 < NN - 8; n0 += 8) {
            const float* ap = aptr + (size_t)(n0 + 8) * NN;
            const float* np = &nu_s[(n0 + 8) * 32 + w * 4];
            #pragma unroll
            for (int k = 0; k < 8; k++) {
                float  a_n = __ldg(ap + (size_t)k * NN);
                float4 p_n = *(const float4*)(np + k * 32);
                acc[0] = fmaf(p_r[k].x, a_r[k], acc[0]);
                acc[1] = fmaf(p_r[k].y, a_r[k], acc[1]);
                acc[2] = fmaf(p_r[k].z, a_r[k], acc[2]);
                acc[3] = fmaf(p_r[k].w, a_r[k], acc[3]);
                a_r[k] = a_n;
                p_r[k] = p_n;
            }
        }
        // final 8 (already prefetched)
        #pragma unroll
        for (int k = 0; k < 8; k++) {
            acc[0] = fmaf(p_r[k].x, a_r[k], acc[0]);
            acc[1] = fmaf(p_r[k].y, a_r[k], acc[1]);
            acc[2] = fmaf(p_r[k].z, a_r[k], acc[2]);
            acc[3] = fmaf(p_r[k].w, a_r[k], acc[3]);
        }
    }

    float xv = x[b * NN + j];
    float ev = extra[b * NN + j];

    float mu[4];
    #pragma unroll
    for (int i = 0; i < 4; i++) {
        const float* t1p = t1 + (layer * PP + w * 4 + i) * 3;
        float c0 = t1p[0], c1 = t1p[1], c2 = t1p[2];
        mu[i] = acc[i] + fmaf(c0, 1.0f - xv, fmaf(c2, ev, c1));
    }
    #pragma unroll
    for (int q = 0; q < PP; q++) {
        float4 t3v = *(const float4*)&t3t_s[q * 36 + w * 4];
        float tv = t31_s[lane * 33 + q];
        mu[0] = fmaf(t3v.x, tv, mu[0]);
        mu[1] = fmaf(t3v.y, tv, mu[1]);
        mu[2] = fmaf(t3v.z, tv, mu[2]);
        mu[3] = fmaf(t3v.w, tv, mu[3]);
    }
    #pragma unroll
    for (int i = 0; i < 4; i++) mu[i] = fmaxf(mu[i], 0.0f);

    if (layer == 2) {
        #pragma unroll
        for (int i = 0; i < 4; i++)
            out[((size_t)b * PP + w * 4 + i) * NN + j] = mu[i];
        return;
    }

    // mu_s[jl][q] for nu computation
    #pragma unroll
    for (int i = 0; i < 4; i++)
        mu_s[lane * 33 + w * 4 + i] = mu[i];
    __syncthreads();

    float nu[4] = {0.f, 0.f, 0.f, 0.f};
    #pragma unroll
    for (int q = 0; q < PP; q++) {
        float4 t2v = *(const float4*)&t2n_s[q * 36 + w * 4];
        float m = mu_s[lane * 33 + q];
        nu[0] = fmaf(t2v.x, m, nu[0]);
        nu[1] = fmaf(t2v.y, m, nu[1]);
        nu[2] = fmaf(t2v.z, m, nu[2]);
        nu[3] = fmaf(t2v.w, m, nu[3]);
    }

    // write transposed: g_nu[b][j][p], float4 over p
    float4 nv = make_float4(nu[0], nu[1], nu[2], nu[3]);
    *(float4*)(g_nu + ((size_t)b * NN + j) * 32 + w * 4) = nv;
}

// ---------------------------------------------------------------------------
extern "C" void kernel_launch(void* const* d_in, const int* in_sizes, int n_in,
                              void* d_out, int out_size)
{
    const float* x     = (const float*)d_in[0];
    const float* adj   = (const float*)d_in[1];
    const float* wgt   = (const float*)d_in[2];
    const float* extra = (const float*)d_in[3];
    const float* t1    = (const float*)d_in[4];
    const float* t2    = (const float*)d_in[5];
    const float* t3    = (const float*)d_in[6];
    const float* t4    = (const float*)d_in[7];
    float* out = (float*)d_out;

    static const size_t smem_bytes = SM_TOT * sizeof(float);
    cudaFuncSetAttribute(layer_kernel,
                         cudaFuncAttributeMaxDynamicSharedMemorySize,
                         (int)smem_bytes);

    dim3 edge_grid(NN, BB);
    dim3 lay_grid(16, BB);

    edge_kernel<<<edge_grid, 256>>>(x, wgt, t4);

    // layer 0: no z; writes g_nu = t2[1] @ mu0 (transposed)
    layer_kernel<<<lay_grid, 256, smem_bytes>>>(x, extra, adj, t1, t2, t3, 0, 0, out);
    // layer 1: z = nu@adj; writes g_nu = t2[2] @ mu1
    layer_kernel<<<lay_grid, 256, smem_bytes>>>(x, extra, adj, t1, t2, t3, 1, 1, out);
    // layer 2: z = nu@adj; writes mu2 -> out
    layer_kernel<<<lay_grid, 256, smem_bytes>>>(x, extra, adj, t1, t2, t3, 2, 1, out);
}

// round 14
// speedup vs baseline: 1.2577x; 1.2577x over previous
#include <cuda_runtime.h>

#define BB 8
#define NN 512
#define PP 32
#define LL 3

typedef unsigned long long ull;

// Scratch (device globals: no allocation in kernel_launch)
__device__ float g_t31[LL][BB*NN*PP];      // [l][b][n][p]
__device__ float g_nu[BB*NN*PP];           // TRANSPOSED: [b][n][p] = (t2[l]@mu_{l-1})[p][n]

// ---- packed f32x2 helpers (sm_100+) ---------------------------------------
__device__ __forceinline__ ull pk(float lo, float hi) {
    ull r; asm("mov.b64 %0,{%1,%2};" : "=l"(r) : "f"(lo), "f"(hi)); return r;
}
__device__ __forceinline__ void upk(ull v, float& lo, float& hi) {
    asm("mov.b64 {%0,%1},%2;" : "=f"(lo), "=f"(hi) : "l"(v));
}
__device__ __forceinline__ ull fma2(ull a, ull b, ull c) {
    ull d; asm("fma.rn.f32x2 %0,%1,%2,%3;" : "=l"(d) : "l"(a), "l"(b), "l"(c));
    return d;
}
__device__ __forceinline__ ull add2(ull a, ull b) {
    ull d; asm("add.rn.f32x2 %0,%1,%2;" : "=l"(d) : "l"(a), "l"(b));
    return d;
}

union F4U2 { float4 f4; ull u2[2]; };

// ---- cp.async helpers ------------------------------------------------------
__device__ __forceinline__ void cp16(float* smem_dst, const float* gsrc) {
    unsigned d = (unsigned)__cvta_generic_to_shared(smem_dst);
    asm volatile("cp.async.ca.shared.global [%0], [%1], 16;"
                 :: "r"(d), "l"(gsrc));
}
__device__ __forceinline__ void cp_commit() {
    asm volatile("cp.async.commit_group;");
}
template <int N>
__device__ __forceinline__ void cp_wait() {
    asm volatile("cp.async.wait_group %0;" :: "n"(N));
}

// ---------------------------------------------------------------------------
// K1 (fused over layers): t31[l][b][n][p] = sum_m relu(A + B*w + C*s)
//   = 0.5*(Sum v + Sum|v|);  Sum v closed-form via row sums.
// grid (N, B), block 256. lane = p; 8 warps split m; 3 layers interleaved.
// ---------------------------------------------------------------------------
__global__ __launch_bounds__(256) void edge_kernel(
    const float* __restrict__ x, const float* __restrict__ wgt,
    const float* __restrict__ t4)
{
    __shared__ float w_s[NN];
    __shared__ float s_s[NN];
    __shared__ float red_s[LL][8][PP];
    __shared__ float rw_s[8], rs_s[8];

    int n = blockIdx.x, b = blockIdx.y;
    int tid = threadIdx.x;
    int lane = tid & 31;
    int wid  = tid >> 5;

    const float* wrow = wgt + ((size_t)(b * NN + n)) * NN;
    const float* xb   = x + b * NN;

    float pw = 0.f, ps = 0.f;
    for (int m = tid; m < NN; m += 256) {
        float w = wrow[m];
        float s = 2.0f * xb[m] - 1.0f;
        w_s[m] = w;
        s_s[m] = s;
        pw += w;
        ps += s;
    }
    #pragma unroll
    for (int o = 16; o; o >>= 1) {
        pw += __shfl_xor_sync(0xffffffffu, pw, o);
        ps += __shfl_xor_sync(0xffffffffu, ps, o);
    }
    if (lane == 0) { rw_s[wid] = pw; rs_s[wid] = ps; }

    float xn = xb[n];
    float sn = 2.0f * xn - 1.0f;

    float As[LL], Bs[LL], Cs[LL];
    ull A2[LL], B2[LL], C2[LL];
    #pragma unroll
    for (int l = 0; l < LL; l++) {
        const float* t4p = t4 + (l * PP + lane) * 4;
        float c0 = t4p[0], c1 = t4p[1], c2 = t4p[2], c3 = t4p[3];
        float A  = fmaf(c0, xn, fmaf(0.5f, c2, c3));
        float C  = -0.5f * c2 * sn;
        As[l] = A; Bs[l] = c1; Cs[l] = C;
        A2[l] = pk(A, A);
        B2[l] = pk(c1, c1);
        C2[l] = pk(C, C);
    }

    __syncthreads();

    float sw = 0.f, ss = 0.f;
    #pragma unroll
    for (int k = 0; k < 8; k++) { sw += rw_s[k]; ss += rs_s[k]; }

    const ull ABSM = 0x7fffffff7fffffffULL;
    ull sa[LL] = {0, 0, 0};   // packed sum of |v|

    int m0 = wid * (NN / 8);
    #pragma unroll 4
    for (int m = m0; m < m0 + NN / 8; m += 4) {
        F4U2 w4, s4;
        w4.f4 = *(const float4*)(w_s + m);
        s4.f4 = *(const float4*)(s_s + m);
        #pragma unroll
        for (int l = 0; l < LL; l++) {
            ull v0 = fma2(C2[l], s4.u2[0], fma2(B2[l], w4.u2[0], A2[l]));
            ull v1 = fma2(C2[l], s4.u2[1], fma2(B2[l], w4.u2[1], A2[l]));
            sa[l] = add2(sa[l], add2(v0 & ABSM, v1 & ABSM));
        }
    }

    #pragma unroll
    for (int l = 0; l < LL; l++) {
        float a, bb;
        upk(sa[l], a, bb);
        red_s[l][wid][lane] = a + bb;
    }
    __syncthreads();

    if (wid < LL) {
        int l = wid;
        float stot = red_s[l][0][lane];
        #pragma unroll
        for (int k = 1; k < 8; k++) stot += red_s[l][k][lane];
        float sv = fmaf(512.0f, As[l], fmaf(Bs[l], sw, Cs[l] * ss));
        g_t31[l][(b * NN + n) * PP + lane] = 0.5f * (sv + stot);
    }
}

// ---------------------------------------------------------------------------
// K2 (per layer): full-n z + epilogue + next-layer nu, one block per (jt, b).
//   z[p][j]  = sum_n nu[b][n][p] * adj[b][n][j]       (has_z)
//   mu[p][j] = relu( term1 + z + sum_q t3[l][p][q]*t31[l][q][j] )
//   layer<2:  g_nu[b][j][p] = sum_q t2[l+1][p][q]*mu[q][j]
//   layer==2: out[b][p][j] = mu
// grid (16, 8), block 256 = TWO half-blocks over the same 32p x 32j tile:
//   nh = tid>>7 selects n-half [nh*256, nh*256+256); within a half (t=tid&127):
//   pg = w4 + 4*(lane>>4) (p = 4pg..4pg+3), jp = lane&15 (j = j0+2jp, +1).
// Full adj+nu strips staged once via cp.async; mainloop barrier-free;
// cross-half reduction through smem at the end.
// ---------------------------------------------------------------------------
#define SM_A    0                      // a_s  [512][32]
#define SM_NU   (NN*32)                // nu_s [512][32]
#define SM_T31  (2*NN*32)              // t31_s [32][33]   (scalar reads)
#define SM_T3   (SM_T31 + 32*33)       // t3t_s [32][36]   (float4 reads)
#define SM_T2N  (SM_T3 + 32*36)        // t2n_s [32][36]   (float4 reads)
#define SM_MU   (SM_T2N + 32*36)       // mu_s  [32][33]   (scalar reads)
#define SM_TOT  (SM_MU + 32*33)        // floats (~145KB)

__global__ void __launch_bounds__(256, 1) layer_kernel(
    const float* __restrict__ x, const float* __restrict__ extra,
    const float* __restrict__ adj,
    const float* __restrict__ t1, const float* __restrict__ t2,
    const float* __restrict__ t3, int layer, int has_z,
    float* __restrict__ out)
{
    extern __shared__ float sm[];
    float* a_s   = sm + SM_A;
    float* nu_s  = sm + SM_NU;
    float* t31_s = sm + SM_T31;
    float* t3t_s = sm + SM_T3;
    float* t2n_s = sm + SM_T2N;
    float* mu_s  = sm + SM_MU;

    int jt = blockIdx.x, b = blockIdx.y;
    int tid  = threadIdx.x;
    int nh   = tid >> 7;               // n-half: 0 or 1
    int t    = tid & 127;
    int lane = t & 31;
    int w4   = t >> 5;                 // 0..3
    int j0   = jt * 32;
    int pg   = w4 + 4 * (lane >> 4);   // 0..7, p = 4*pg..4*pg+3
    int jp   = lane & 15;              // j local = 2*jp, 2*jp+1

    float acc[4][2];
    #pragma unroll
    for (int i = 0; i < 4; i++) { acc[i][0] = 0.f; acc[i][1] = 0.f; }

    if (has_z) {
        // stage full adj + nu strips [512][32] each: 4096 cp16 pairs / 256 thr
        #pragma unroll
        for (int pass = 0; pass < 16; pass++) {
            int i = tid + pass * 256;            // 0..4095
            int row = i >> 3;                    // 0..511
            int seg = (i & 7) * 4;
            cp16(&a_s[row * 32 + seg],
                 adj + ((size_t)(b * NN + row)) * NN + j0 + seg);
            cp16(&nu_s[row * 32 + seg],
                 g_nu + ((size_t)(b * NN + row)) * 32 + seg);
        }
        cp_commit();
    }

    // stage epilogue tiles (plain loads; overlap with cp.async)
    #pragma unroll
    for (int pass = 0; pass < 4; pass++) {
        int idx = tid + pass * 256;               // jl*32 + q
        int jl = idx >> 5, q = idx & 31;
        t31_s[jl * 33 + q] = g_t31[layer][((size_t)b * NN + j0 + jl) * PP + q];
    }
    #pragma unroll
    for (int pass = 0; pass < 4; pass++) {
        int idx = tid + pass * 256;               // p*32 + q
        int p = idx >> 5, q = idx & 31;
        t3t_s[q * 36 + p] = t3[layer * PP * PP + idx];
        if (layer < 2)
            t2n_s[q * 36 + p] = t2[(layer + 1) * PP * PP + idx];
    }

    if (has_z) cp_wait<0>();
    __syncthreads();

    if (has_z) {
        int nbase = nh * 256;
        // barrier-free mainloop: 256 n per half, 2 warps/SMSP interleave
        #pragma unroll 8
        for (int nn = 0; nn < 256; nn++) {
            int n = nbase + nn;
            float2 a2 = *(const float2*)&a_s[n * 32 + jp * 2];
            float4 p4 = *(const float4*)&nu_s[n * 32 + pg * 4];
            acc[0][0] = fmaf(p4.x, a2.x, acc[0][0]);
            acc[0][1] = fmaf(p4.x, a2.y, acc[0][1]);
            acc[1][0] = fmaf(p4.y, a2.x, acc[1][0]);
            acc[1][1] = fmaf(p4.y, a2.y, acc[1][1]);
            acc[2][0] = fmaf(p4.z, a2.x, acc[2][0]);
            acc[2][1] = fmaf(p4.z, a2.y, acc[2][1]);
            acc[3][0] = fmaf(p4.w, a2.x, acc[3][0]);
            acc[3][1] = fmaf(p4.w, a2.y, acc[3][1]);
        }

        // cross-half reduction via smem (reuse a_s region)
        __syncthreads();
        if (nh == 1) {
            float* r = &a_s[t * 8];
            #pragma unroll
            for (int i = 0; i < 4; i++) {
                r[i * 2 + 0] = acc[i][0];
                r[i * 2 + 1] = acc[i][1];
            }
        }
        __syncthreads();
        if (nh == 0) {
            const float* r = &a_s[t * 8];
            #pragma unroll
            for (int i = 0; i < 4; i++) {
                acc[i][0] += r[i * 2 + 0];
                acc[i][1] += r[i * 2 + 1];
            }
        }
    }

    // epilogue (half 0 only; half 1 idles through the barriers)
    float mu[4][2];
    if (nh == 0) {
        int jg0 = j0 + jp * 2;
        float xv0 = x[b * NN + jg0],     xv1 = x[b * NN + jg0 + 1];
        float ev0 = extra[b * NN + jg0], ev1 = extra[b * NN + jg0 + 1];

        #pragma unroll
        for (int i = 0; i < 4; i++) {
            const float* t1p = t1 + (layer * PP + pg * 4 + i) * 3;
            float c0 = t1p[0], c1 = t1p[1], c2 = t1p[2];
            mu[i][0] = acc[i][0] + fmaf(c0, 1.0f - xv0, fmaf(c2, ev0, c1));
            mu[i][1] = acc[i][1] + fmaf(c0, 1.0f - xv1, fmaf(c2, ev1, c1));
        }
        #pragma unroll
        for (int q = 0; q < PP; q++) {
            float4 t3v = *(const float4*)&t3t_s[q * 36 + pg * 4];
            const float t3a[4] = {t3v.x, t3v.y, t3v.z, t3v.w};
            float tv0 = t31_s[(jp * 2) * 33 + q];
            float tv1 = t31_s[(jp * 2 + 1) * 33 + q];
            #pragma unroll
            for (int i = 0; i < 4; i++) {
                mu[i][0] = fmaf(t3a[i], tv0, mu[i][0]);
                mu[i][1] = fmaf(t3a[i], tv1, mu[i][1]);
            }
        }
        #pragma unroll
        for (int i = 0; i < 4; i++) {
            mu[i][0] = fmaxf(mu[i][0], 0.0f);
            mu[i][1] = fmaxf(mu[i][1], 0.0f);
        }
    }

    if (layer == 2) {
        if (nh == 0) {
            int jg0 = j0 + jp * 2;
            #pragma unroll
            for (int i = 0; i < 4; i++) {
                float2 r = make_float2(mu[i][0], mu[i][1]);
                *(float2*)(out + ((size_t)b * PP + pg * 4 + i) * NN + jg0) = r;
            }
        }
        return;
    }

    if (nh == 0) {
        #pragma unroll
        for (int i = 0; i < 4; i++) {
            mu_s[(jp * 2) * 33 + pg * 4 + i]     = mu[i][0];
            mu_s[(jp * 2 + 1) * 33 + pg * 4 + i] = mu[i][1];
        }
    }
    __syncthreads();

    if (nh == 0) {
        float nu[4][2];
        #pragma unroll
        for (int i = 0; i < 4; i++) { nu[i][0] = 0.f; nu[i][1] = 0.f; }
        #pragma unroll
        for (int q = 0; q < PP; q++) {
            float4 t2v = *(const float4*)&t2n_s[q * 36 + pg * 4];
            const float t2a[4] = {t2v.x, t2v.y, t2v.z, t2v.w};
            float m0 = mu_s[(jp * 2) * 33 + q];
            float m1 = mu_s[(jp * 2 + 1) * 33 + q];
            #pragma unroll
            for (int i = 0; i < 4; i++) {
                nu[i][0] = fmaf(t2a[i], m0, nu[i][0]);
                nu[i][1] = fmaf(t2a[i], m1, nu[i][1]);
            }
        }
        int jg0 = j0 + jp * 2;
        float4 n0 = make_float4(nu[0][0], nu[1][0], nu[2][0], nu[3][0]);
        float4 n1 = make_float4(nu[0][1], nu[1][1], nu[2][1], nu[3][1]);
        *(float4*)(g_nu + ((size_t)b * NN + jg0) * 32 + pg * 4)     = n0;
        *(float4*)(g_nu + ((size_t)b * NN + jg0 + 1) * 32 + pg * 4) = n1;
    }
}

// ---------------------------------------------------------------------------
extern "C" void kernel_launch(void* const* d_in, const int* in_sizes, int n_in,
                              void* d_out, int out_size)
{
    const float* x     = (const float*)d_in[0];
    const float* adj   = (const float*)d_in[1];
    const float* wgt   = (const float*)d_in[2];
    const float* extra = (const float*)d_in[3];
    const float* t1    = (const float*)d_in[4];
    const float* t2    = (const float*)d_in[5];
    const float* t3    = (const float*)d_in[6];
    const float* t4    = (const float*)d_in[7];
    float* out = (float*)d_out;

    static const size_t smem_bytes = SM_TOT * sizeof(float);
    cudaFuncSetAttribute(layer_kernel,
                         cudaFuncAttributeMaxDynamicSharedMemorySize,
                         (int)smem_bytes);

    dim3 edge_grid(NN, BB);
    dim3 lay_grid(16, BB);

    edge_kernel<<<edge_grid, 256>>>(x, wgt, t4);

    // layer 0: no z; writes g_nu = t2[1] @ mu0 (transposed)
    layer_kernel<<<lay_grid, 256, smem_bytes>>>(x, extra, adj, t1, t2, t3, 0, 0, out);
    // layer 1: z = nu@adj; writes g_nu = t2[2] @ mu1
    layer_kernel<<<lay_grid, 256, smem_bytes>>>(x, extra, adj, t1, t2, t3, 1, 1, out);
    // layer 2: z = nu@adj; writes mu2 -> out
    layer_kernel<<<lay_grid, 256, smem_bytes>>>(x, extra, adj, t1, t2, t3, 2, 1, out);
}